// round 3
// baseline (speedup 1.0000x reference)
#include <cuda_runtime.h>
#include <cuda_bf16.h>
#include <cstdint>

#define B_     4
#define GXF    480            // full output x
#define GXC    360            // compact x (pt_ind in [0,360))
#define GY_    360
#define CIN_   64
#define COUT_  32
#define NPT    480000
#define NVOX   (B_ * GXC * GY_)        // 518400 compact voxels
#define SCAN_BLK 1024
#define NB1    ((NVOX + SCAN_BLK - 1) / SCAN_BLK)   // 507

__device__ unsigned int d_cnt[NVOX];
__device__ unsigned int d_cursor[NVOX];
__device__ unsigned int d_blockSums[NB1];
__device__ unsigned int d_blockOff[NB1];
__device__ unsigned int d_seg[NPT];
__device__ unsigned int d_pack[NPT];      // (point_idx << 7) | vloc_in_tile

__device__ __forceinline__ unsigned int enc_f32(float f) {
    unsigned int u = __float_as_uint(f);
    return (u & 0x80000000u) ? ~u : (u | 0x80000000u);
}
__device__ __forceinline__ float dec_f32(unsigned int u) {
    return (u & 0x80000000u) ? __uint_as_float(u ^ 0x80000000u)
                             : __uint_as_float(~u);
}

// -------- Z: zero counters + zero output band x in [360,480) --------
__global__ void zero_kernel(float* __restrict__ out) {
    int g = blockIdx.x * blockDim.x + threadIdx.x;
    const int nCnt4 = NVOX / 4;                              // 129600
    const int per   = (GXF - GXC) * GY_ / 4;                 // 10800 float4 per (b,co)
    const int nBand = B_ * COUT_ * per;                      // 1,382,400
    if (g < nCnt4) {
        reinterpret_cast<uint4*>(d_cnt)[g] = make_uint4(0u,0u,0u,0u);
    } else if (g < nCnt4 + nBand) {
        int gg = g - nCnt4;
        int c   = gg / per;
        int off = gg % per;
        float4* p = reinterpret_cast<float4*>(
            out + (size_t)c * GXF * GY_ + (size_t)GXC * GY_);
        p[off] = make_float4(0.f, 0.f, 0.f, 0.f);
    }
}

// -------- A: seg id + histogram --------
__global__ void count_kernel(const int* __restrict__ ind,
                             const int* __restrict__ bidx) {
    int i = blockIdx.x * blockDim.x + threadIdx.x;
    if (i >= NPT) return;
    int2 xy = reinterpret_cast<const int2*>(ind)[i];
    int b = bidx[i];
    unsigned int s = (unsigned)((b * GXC + xy.x) * GY_ + xy.y);
    d_seg[i] = s;
    atomicAdd(&d_cnt[s], 1u);
}

// -------- B: block-wise exclusive scan --------
__global__ void scan_block_kernel(const unsigned int* __restrict__ in,
                                  unsigned int* __restrict__ out,
                                  unsigned int* bs, int n) {
    __shared__ unsigned int wsum[32];
    int tid = threadIdx.x, lane = tid & 31, wid = tid >> 5;
    int gid = blockIdx.x * SCAN_BLK + tid;
    unsigned int x = (gid < n) ? in[gid] : 0u;
    unsigned int inc = x;
    #pragma unroll
    for (int d = 1; d < 32; d <<= 1) {
        unsigned int v = __shfl_up_sync(0xFFFFFFFFu, inc, d);
        if (lane >= d) inc += v;
    }
    if (lane == 31) wsum[wid] = inc;
    __syncthreads();
    if (wid == 0) {
        unsigned int v = wsum[lane];
        #pragma unroll
        for (int d = 1; d < 32; d <<= 1) {
            unsigned int t = __shfl_up_sync(0xFFFFFFFFu, v, d);
            if (lane >= d) v += t;
        }
        wsum[lane] = v;
    }
    __syncthreads();
    unsigned int warpOff = (wid > 0) ? wsum[wid - 1] : 0u;
    if (gid < n) out[gid] = warpOff + inc - x;
    if (tid == SCAN_BLK - 1 && bs) bs[blockIdx.x] = warpOff + inc;
}

// -------- B3: add block offsets --------
__global__ void scan_add_kernel() {
    int gid = blockIdx.x * SCAN_BLK + threadIdx.x;
    if (gid < NVOX) d_cursor[gid] += d_blockOff[blockIdx.x];
}

// -------- C: scatter packed (idx,vloc); cursor -> per-voxel end ----------
__global__ void scatter_kernel() {
    int i = blockIdx.x * blockDim.x + threadIdx.x;
    if (i >= NPT) return;
    unsigned int s = d_seg[i];
    unsigned int pos = atomicAdd(&d_cursor[s], 1u);
    d_pack[pos] = ((unsigned)i << 7) | (s & 127u);
}

// -------- D: fused segment-max + Linear(64->32) + ReLU + transposed store --
__global__ __launch_bounds__(256) void fused_kernel(
        const float* __restrict__ fea,
        const float* __restrict__ W,
        const float* __restrict__ bias,
        float* __restrict__ out) {
    __shared__ unsigned int uPool[128 * 65];   // encoded max, 0 == empty
    __shared__ float sW[CIN_ * COUT_];
    __shared__ float sB[COUT_];
    __shared__ int sS, sE;

    const int tid  = threadIdx.x;
    const int base = blockIdx.x * 128;
    const int wid  = tid >> 5, lane = tid & 31;

    #pragma unroll
    for (int i = tid; i < CIN_ * COUT_; i += 256) sW[i] = W[i];
    if (tid < COUT_) sB[tid] = bias[tid];
    #pragma unroll
    for (int i = tid; i < 128 * 65 / 4; i += 256)
        reinterpret_cast<uint4*>(uPool)[i] = make_uint4(0u,0u,0u,0u);
    if (tid == 0) {
        sE = (int)d_cursor[base + 127];
        sS = (int)(d_cursor[base] - d_cnt[base]);
    }
    __syncthreads();

    // ---- Phase 1: register-run segment max over sorted points ----
    {
        const int S = sS, E = sE;
        const int total = E - S;
        const int chunk = (total + 7) >> 3;                 // per warp
        const int ws = S + wid * chunk;
        const int we = min(ws + chunk, E);

        int   curV = -1;
        float mx0 = 0.f, mx1 = 0.f;
        for (int p0 = ws; p0 < we; p0 += 32) {
            unsigned int pk = 0u;
            if (p0 + lane < we) pk = d_pack[p0 + lane];
            int m = min(32, we - p0);
            for (int j = 0; j < m; j++) {
                unsigned int u = __shfl_sync(0xFFFFFFFFu, pk, j);
                int vloc = (int)(u & 127u);
                int idx  = (int)(u >> 7);
                float2 v = reinterpret_cast<const float2*>(
                               fea + (size_t)idx * CIN_)[lane];
                if (vloc != curV) {
                    if (curV >= 0) {
                        atomicMax(&uPool[curV * 65 + 2*lane],     enc_f32(mx0));
                        atomicMax(&uPool[curV * 65 + 2*lane + 1], enc_f32(mx1));
                    }
                    curV = vloc; mx0 = v.x; mx1 = v.y;
                } else {
                    mx0 = fmaxf(mx0, v.x);
                    mx1 = fmaxf(mx1, v.y);
                }
            }
        }
        if (curV >= 0) {
            atomicMax(&uPool[curV * 65 + 2*lane],     enc_f32(mx0));
            atomicMax(&uPool[curV * 65 + 2*lane + 1], enc_f32(mx1));
        }
    }
    __syncthreads();

    // ---- Phase 2: 2 threads/voxel, 16 outputs each, f32x2 FMA ----
    const int v    = tid & 127;
    const int half = tid >> 7;
    const int cv   = base + v;
    const int bi   = cv / (GXC * GY_);
    const int rem  = cv % (GXC * GY_);
    const int x    = rem / GY_;
    const int y    = rem % GY_;
    float* optr = out + (((size_t)bi * COUT_ + half * 16) * GXF + x) * GY_ + y;
    const size_t cs = (size_t)GXF * GY_;

    if (uPool[v * 65] == 0u) {                 // empty voxel
        #pragma unroll
        for (int j = 0; j < 16; j++) optr[j * cs] = 0.0f;
        return;
    }

    unsigned long long acc2[8];
    #pragma unroll
    for (int j = 0; j < 8; j++) {
        float blo = sB[half * 16 + 2*j];
        float bhi = sB[half * 16 + 2*j + 1];
        asm("mov.b64 %0, {%1, %2};" : "=l"(acc2[j]) : "f"(blo), "f"(bhi));
    }

    const unsigned int* myRow = &uPool[v * 65];
    #pragma unroll 4
    for (int c = 0; c < CIN_; c++) {
        float pv = dec_f32(myRow[c]);
        unsigned long long pvv;
        asm("mov.b64 %0, {%1, %2};" : "=l"(pvv) : "f"(pv), "f"(pv));
        const ulonglong2* w2 = reinterpret_cast<const ulonglong2*>(
            &sW[c * COUT_ + half * 16]);
        #pragma unroll
        for (int j = 0; j < 4; j++) {
            ulonglong2 w = w2[j];
            asm("fma.rn.f32x2 %0, %1, %2, %3;"
                : "=l"(acc2[2*j])   : "l"(pvv), "l"(w.x), "l"(acc2[2*j]));
            asm("fma.rn.f32x2 %0, %1, %2, %3;"
                : "=l"(acc2[2*j+1]) : "l"(pvv), "l"(w.y), "l"(acc2[2*j+1]));
        }
    }
    #pragma unroll
    for (int j = 0; j < 8; j++) {
        float lo, hi;
        asm("mov.b64 {%0, %1}, %2;" : "=f"(lo), "=f"(hi) : "l"(acc2[j]));
        optr[(2*j)   * cs] = fmaxf(lo, 0.0f);
        optr[(2*j+1) * cs] = fmaxf(hi, 0.0f);
    }
}

extern "C" void kernel_launch(void* const* d_in, const int* in_sizes, int n_in,
                              void* d_out, int out_size) {
    const float* pt_fea   = (const float*)d_in[0];
    const int*   pt_ind   = (const int*)  d_in[1];
    const int*   batch_ix = (const int*)  d_in[2];
    const float* W_comp   = (const float*)d_in[3];
    const float* b_comp   = (const float*)d_in[4];
    float*       out      = (float*)d_out;

    unsigned int *p_cnt, *p_cursor, *p_bs, *p_boff;
    cudaGetSymbolAddress((void**)&p_cnt,    d_cnt);
    cudaGetSymbolAddress((void**)&p_cursor, d_cursor);
    cudaGetSymbolAddress((void**)&p_bs,     d_blockSums);
    cudaGetSymbolAddress((void**)&p_boff,   d_blockOff);

    {
        const int nZero = NVOX/4 + B_*COUT_*((GXF-GXC)*GY_/4);
        zero_kernel<<<(nZero + 255)/256, 256>>>(out);
    }
    count_kernel<<<(NPT + 255)/256, 256>>>(pt_ind, batch_ix);
    scan_block_kernel<<<NB1, SCAN_BLK>>>(p_cnt, p_cursor, p_bs, NVOX);
    scan_block_kernel<<<1,   SCAN_BLK>>>(p_bs,  p_boff, nullptr, NB1);
    scan_add_kernel<<<NB1, SCAN_BLK>>>();
    scatter_kernel<<<(NPT + 255)/256, 256>>>();
    fused_kernel<<<NVOX/128, 256>>>(pt_fea, W_comp, b_comp, out);
}